// round 1
// baseline (speedup 1.0000x reference)
#include <cuda_runtime.h>

// Problem constants
#define S   32            // spatial size
#define SP  34            // padded size
#define SPP (SP*SP)       // 1156
#define NC  16            // channels (in and out)
#define VOX (S*S*S)       // 32768

// Scratch: padded, channels-last copy of x: [34][34][34][16] floats = 2.51 MB
__device__ float g_xp[SP*SP*SP*NC];

// ---------------------------------------------------------------------------
// Kernel 1: pad + transpose x [C][32][32][32] -> g_xp [34][34][34][C]
// One thread per padded spatial position; coalesced reads per channel,
// fully-coalesced 64B float4 stores.
// ---------------------------------------------------------------------------
__global__ void pad_transpose_kernel(const float* __restrict__ x) {
    int sp = blockIdx.x * blockDim.x + threadIdx.x;
    if (sp >= SP*SP*SP) return;
    int z  = sp % SP;
    int t2 = sp / SP;
    int y  = t2 % SP;
    int xx = t2 / SP;
    bool inb = (xx >= 1 && xx <= S && y >= 1 && y <= S && z >= 1 && z <= S);
    int src = (xx-1)*(S*S) + (y-1)*S + (z-1);
    float4* dst = (float4*)(g_xp + sp * NC);
#pragma unroll
    for (int cq = 0; cq < 4; cq++) {
        float4 v = make_float4(0.f, 0.f, 0.f, 0.f);
        if (inb) {
            v.x = x[(cq*4 + 0) * VOX + src];
            v.y = x[(cq*4 + 1) * VOX + src];
            v.z = x[(cq*4 + 2) * VOX + src];
            v.w = x[(cq*4 + 3) * VOX + src];
        }
        dst[cq] = v;
    }
}

// ---------------------------------------------------------------------------
// Kernel 2: fused deformable sampling + conv (gather formulation).
// 4 lanes per output voxel; lane cpart owns input channels [4*cpart, 4*cpart+4).
// CTA = 256 threads = 64 output voxels. Grid = 512 CTAs.
// ---------------------------------------------------------------------------
__global__ void __launch_bounds__(256)
deform_conv3d_kernel(const float* __restrict__ off,
                     const float* __restrict__ wgt,
                     float* __restrict__ out)
{
    // shared weights: ws[abc][co][ci], abc = a*9+b*3+c
    __shared__ __align__(16) float ws[27*16*16];
    int tid = threadIdx.x;
    for (int idx = tid; idx < 27*16*16; idx += 256) {
        int abc = idx >> 8;
        int co  = (idx >> 4) & 15;
        int ci  = idx & 15;
        ws[idx] = wgt[co*432 + ci*27 + abc];
    }
    __syncthreads();

    const int cpart = tid & 3;
    const int v  = blockIdx.x * 64 + (tid >> 2);   // output voxel (linear)
    const int oh = v >> 10;
    const int ow = (v >> 5) & 31;
    const int od = v & 31;

    float acc[16];
#pragma unroll
    for (int i = 0; i < 16; i++) acc[i] = 0.f;

    const float4* __restrict__ xp4 = (const float4*)g_xp;

#pragma unroll 1
    for (int a = 0; a < 3; a++) {
        int aw    = a * 32 + ow;
        int w_src = aw / 3;
        int r1    = aw - w_src * 3;
        int u     = r1 * 32 + od;
        int d_src = u / 3;
        int j     = u - d_src * 3;
        int vsrc  = (oh * 32 + w_src) * 32 + d_src;

        float bx = (float)(oh    + 1);
        float by = (float)(w_src + 1);
        float bz = (float)(d_src + 1);

#pragma unroll 1
        for (int b = 0; b < 3; b++) {
#pragma unroll 1
            for (int c = 0; c < 3; c++) {
                int n = 9*b + 3*j + c;
                float ox = off[ n        * VOX + vsrc];
                float oy = off[(n + 27) * VOX + vsrc];
                float oz = off[(n + 54) * VOX + vsrc];

                float px = bx + (float)(b - 1) + ox;
                float py = by + (float)(j - 1) + oy;
                float pz = bz + (float)(c - 1) + oz;

                // per-axis corners + weights (exact reference semantics)
                float fx = floorf(px), fy = floorf(py), fz = floorf(pz);
                int q0x = min(max((int)fx,     0), SP-1);
                int q1x = min(max((int)fx + 1, 0), SP-1);
                int q0y = min(max((int)fy,     0), SP-1);
                int q1y = min(max((int)fy + 1, 0), SP-1);
                int q0z = min(max((int)fz,     0), SP-1);
                int q1z = min(max((int)fz + 1, 0), SP-1);

                float pxm = (px < 1.f || px > 32.f) ? fx : px;
                float pym = (py < 1.f || py > 32.f) ? fy : py;
                float pzm = (pz < 1.f || pz > 32.f) ? fz : pz;
                pxm = fminf(fmaxf(pxm, 0.f), 33.f);
                pym = fminf(fmaxf(pym, 0.f), 33.f);
                pzm = fminf(fmaxf(pzm, 0.f), 33.f);

                float lx = 1.f + ((float)q0x - pxm);
                float hx = 1.f - ((float)q1x - pxm);
                float ly = 1.f + ((float)q0y - pym);
                float hy = 1.f - ((float)q1y - pym);
                float lz = 1.f + ((float)q0z - pzm);
                float hz = 1.f - ((float)q1z - pzm);

                // float4 indices into channels-last padded x
                int X0 = q0x * (SPP*4), X1 = q1x * (SPP*4);
                int Y0 = q0y * (SP*4),  Y1 = q1y * (SP*4);
                int Z0 = q0z * 4 + cpart, Z1 = q1z * 4 + cpart;

                float4 v000 = xp4[X0 + Y0 + Z0];
                float4 v001 = xp4[X0 + Y0 + Z1];
                float4 v010 = xp4[X0 + Y1 + Z0];
                float4 v011 = xp4[X0 + Y1 + Z1];
                float4 v100 = xp4[X1 + Y0 + Z0];
                float4 v101 = xp4[X1 + Y0 + Z1];
                float4 v110 = xp4[X1 + Y1 + Z0];
                float4 v111 = xp4[X1 + Y1 + Z1];

                float g000 = lx*ly*lz, g001 = lx*ly*hz;
                float g010 = lx*hy*lz, g011 = lx*hy*hz;
                float g100 = hx*ly*lz, g101 = hx*ly*hz;
                float g110 = hx*hy*lz, g111 = hx*hy*hz;

                float4 s;
                s.x = g000*v000.x; s.y = g000*v000.y; s.z = g000*v000.z; s.w = g000*v000.w;
                s.x = fmaf(g001, v001.x, s.x); s.y = fmaf(g001, v001.y, s.y);
                s.z = fmaf(g001, v001.z, s.z); s.w = fmaf(g001, v001.w, s.w);
                s.x = fmaf(g010, v010.x, s.x); s.y = fmaf(g010, v010.y, s.y);
                s.z = fmaf(g010, v010.z, s.z); s.w = fmaf(g010, v010.w, s.w);
                s.x = fmaf(g011, v011.x, s.x); s.y = fmaf(g011, v011.y, s.y);
                s.z = fmaf(g011, v011.z, s.z); s.w = fmaf(g011, v011.w, s.w);
                s.x = fmaf(g100, v100.x, s.x); s.y = fmaf(g100, v100.y, s.y);
                s.z = fmaf(g100, v100.z, s.z); s.w = fmaf(g100, v100.w, s.w);
                s.x = fmaf(g101, v101.x, s.x); s.y = fmaf(g101, v101.y, s.y);
                s.z = fmaf(g101, v101.z, s.z); s.w = fmaf(g101, v101.w, s.w);
                s.x = fmaf(g110, v110.x, s.x); s.y = fmaf(g110, v110.y, s.y);
                s.z = fmaf(g110, v110.z, s.z); s.w = fmaf(g110, v110.w, s.w);
                s.x = fmaf(g111, v111.x, s.x); s.y = fmaf(g111, v111.y, s.y);
                s.z = fmaf(g111, v111.z, s.z); s.w = fmaf(g111, v111.w, s.w);

                // conv accumulate: acc[co] += W[co][ci4] . s  (this lane's 4 ci)
                const float* wp = ws + (a*9 + b*3 + c) * 256 + cpart * 4;
#pragma unroll
                for (int co = 0; co < 16; co++) {
                    float4 wv = *(const float4*)(wp + co * 16);
                    acc[co] = fmaf(wv.x, s.x, acc[co]);
                    acc[co] = fmaf(wv.y, s.y, acc[co]);
                    acc[co] = fmaf(wv.z, s.z, acc[co]);
                    acc[co] = fmaf(wv.w, s.w, acc[co]);
                }
            }
        }
    }

    // reduce partial c_in sums across the 4 lanes of this voxel group
#pragma unroll
    for (int co = 0; co < 16; co++) {
        acc[co] += __shfl_xor_sync(0xffffffffu, acc[co], 1);
        acc[co] += __shfl_xor_sync(0xffffffffu, acc[co], 2);
    }
    // each lane writes 4 output channels (coalesced across the 8 voxel groups)
#pragma unroll
    for (int q = 0; q < 4; q++) {
        int co = cpart * 4 + q;
        out[co * VOX + v] = acc[co];
    }
}

// ---------------------------------------------------------------------------
extern "C" void kernel_launch(void* const* d_in, const int* in_sizes, int n_in,
                              void* d_out, int out_size) {
    const float* x   = (const float*)d_in[0];   // [1,16,32,32,32]
    const float* off = (const float*)d_in[1];   // [1,81,32,32,32]
    const float* wgt = (const float*)d_in[2];   // [16,16,3,3,3]
    float* out = (float*)d_out;                 // [1,16,32,32,32]

    int spTotal = SP*SP*SP;
    pad_transpose_kernel<<<(spTotal + 255) / 256, 256>>>(x);
    deform_conv3d_kernel<<<512, 256>>>(off, wgt, out);
}